// round 15
// baseline (speedup 1.0000x reference)
#include <cuda_runtime.h>
#include <cstdint>

typedef unsigned long long u64;

#define NQ 32768
#define SGRID 32768
#define NEDGE 262144
#define C 192
#define C2 384
#define IDXMASK 32767
#define TILE 64
#define NTHR 384
#define KT 24
#define KTE 12    // k-block for edge kernel (dup-W staging)
#define SROW 68   // floats; 272 B row stride (16B aligned for LDS.128)

// Scratch (device globals; no allocation allowed)
__device__ __align__(16) float g_qe[(size_t)NQ * C];
__device__ __align__(16) float g_u[(size_t)SGRID * C2];    // x @ Cw + cb
__device__ __align__(16) float g_v[(size_t)NQ * C2];       // qe @ W0_bot + b0
__device__ __align__(16) float g_seg[(size_t)NQ * C2];     // seg_sum of h1 (384-wide)
__device__ __align__(16) float g_cw[C * C2];               // proj_w @ W0_top
__device__ __align__(16) float g_cb[C2];                   // proj_b @ W0_top
__device__ int g_cnt[NQ];
__device__ int g_edge64;

// ---------- helpers ----------
__device__ __forceinline__ float gelu_f(float x) {
    return 0.5f * x * (1.0f + erff(x * 0.7071067811865476f));
}
__device__ __forceinline__ void load_edge(const void* Eg, int e, int& q, int& g) {
    if (g_edge64) {
        const long long* E = (const long long*)Eg;
        q = (int)E[2 * (size_t)e] & IDXMASK; g = (int)E[2 * (size_t)e + 1] & IDXMASK;
    } else {
        const int* E = (const int*)Eg;
        q = E[2 * (size_t)e] & IDXMASK; g = E[2 * (size_t)e + 1] & IDXMASK;
    }
}
__device__ __forceinline__ u64 pk2(float lo, float hi) { u64 r; asm("mov.b64 %0,{%1,%2};" : "=l"(r) : "f"(lo), "f"(hi)); return r; }
__device__ __forceinline__ void upk2(u64 v, float& lo, float& hi) { asm("mov.b64 {%0,%1},%2;" : "=f"(lo), "=f"(hi) : "l"(v)); }
__device__ __forceinline__ u64 fma2(u64 a, u64 b, u64 c) { u64 d; asm("fma.rn.f32x2 %0,%1,%2,%3;" : "=l"(d) : "l"(a), "l"(b), "l"(c)); return d; }

// One dense layer on a 64-sample tile in smem ([feature][sample], stride SROW).
// W row-major [KIN][NTOT] in gmem. 384 threads. Exact R9 form (best known).
template<int KIN, int NTOT, bool DOGELU>
__device__ __forceinline__ void layer_mlp(const float* __restrict__ Wg, const float* __restrict__ bg,
                                          const float* src, float* dst, float* wt, int tid)
{
    const int tx = tid % 48, ty = tid / 48;
    int rs[3], cs[3];
    #pragma unroll
    for (int j = 0; j < 3; j++) { int f = tid + j * NTHR; rs[j] = f / 48; cs[j] = (f % 48) * 4; }

    for (int nc = 0; nc < NTOT; nc += 192) {
        u64 acc[4][4];
        #pragma unroll
        for (int p = 0; p < 4; p++)
            #pragma unroll
            for (int ci = 0; ci < 4; ci++) acc[p][ci] = 0ull;

        float4 pf[3];
        #pragma unroll
        for (int j = 0; j < 3; j++)
            pf[j] = *(const float4*)&Wg[(size_t)rs[j] * NTOT + nc + cs[j]];

        for (int kt0 = 0; kt0 < KIN; kt0 += KT) {
            #pragma unroll
            for (int j = 0; j < 3; j++)
                *(float4*)&wt[rs[j] * 192 + cs[j]] = pf[j];
            __syncthreads();
            if (kt0 + KT < KIN) {
                #pragma unroll
                for (int j = 0; j < 3; j++)
                    pf[j] = *(const float4*)&Wg[(size_t)(kt0 + KT + rs[j]) * NTOT + nc + cs[j]];
            }
            #pragma unroll
            for (int kk = 0; kk < KT; kk++) {
                const float* srow = src + (kt0 + kk) * SROW + 8 * ty;
                ulonglong2 aA = *(const ulonglong2*)srow;
                ulonglong2 aB = *(const ulonglong2*)(srow + 4);
                u64 a0 = aA.x, a1 = aA.y, a2 = aB.x, a3 = aB.y;
                float4 bv = *(const float4*)&wt[kk * 192 + tx * 4];
                u64 b0 = pk2(bv.x, bv.x), b1 = pk2(bv.y, bv.y), b2 = pk2(bv.z, bv.z), b3 = pk2(bv.w, bv.w);
                acc[0][0]=fma2(a0,b0,acc[0][0]); acc[0][1]=fma2(a0,b1,acc[0][1]); acc[0][2]=fma2(a0,b2,acc[0][2]); acc[0][3]=fma2(a0,b3,acc[0][3]);
                acc[1][0]=fma2(a1,b0,acc[1][0]); acc[1][1]=fma2(a1,b1,acc[1][1]); acc[1][2]=fma2(a1,b2,acc[1][2]); acc[1][3]=fma2(a1,b3,acc[1][3]);
                acc[2][0]=fma2(a2,b0,acc[2][0]); acc[2][1]=fma2(a2,b1,acc[2][1]); acc[2][2]=fma2(a2,b2,acc[2][2]); acc[2][3]=fma2(a2,b3,acc[2][3]);
                acc[3][0]=fma2(a3,b0,acc[3][0]); acc[3][1]=fma2(a3,b1,acc[3][1]); acc[3][2]=fma2(a3,b2,acc[3][2]); acc[3][3]=fma2(a3,b3,acc[3][3]);
            }
            __syncthreads();
        }
        #pragma unroll
        for (int ci = 0; ci < 4; ci++) {
            int col = nc + tx * 4 + ci;
            float bb = bg[col];
            u64 st[4];
            #pragma unroll
            for (int p = 0; p < 4; p++) {
                float lo, hi; upk2(acc[p][ci], lo, hi);
                lo += bb; hi += bb;
                if (DOGELU) { lo = gelu_f(lo); hi = gelu_f(hi); }
                st[p] = pk2(lo, hi);
            }
            ulonglong2* dp = (ulonglong2*)&dst[(size_t)col * SROW + 8 * ty];
            dp[0] = make_ulonglong2(st[0], st[1]);
            dp[1] = make_ulonglong2(st[2], st[3]);
        }
    }
}

// Edge-layer variant: W staged PRE-DUPLICATED ((w,w) pairs) so the inner loop
// has zero duplication movs: per k-step 4 LDS.128 + 16 FFMA2 only.
// wt layout: [KTE][384]: wt[kk*384 + c*2 .. +1] = (W[k][nc+c], W[k][nc+c]).
template<int KIN, int NTOT, bool DOGELU>
__device__ __forceinline__ void layer_mlp_dup(const float* __restrict__ Wg, const float* __restrict__ bg,
                                              const float* src, float* dst, float* wt, int tid)
{
    const int tx = tid % 48, ty = tid / 48;
    int rs[3], cp[3];
    #pragma unroll
    for (int j = 0; j < 3; j++) { int f = tid + j * NTHR; rs[j] = f / 96; cp[j] = (f % 96) * 2; }

    for (int nc = 0; nc < NTOT; nc += 192) {
        u64 acc[4][4];
        #pragma unroll
        for (int p = 0; p < 4; p++)
            #pragma unroll
            for (int ci = 0; ci < 4; ci++) acc[p][ci] = 0ull;

        float2 pf[3];
        #pragma unroll
        for (int j = 0; j < 3; j++)
            pf[j] = *(const float2*)&Wg[(size_t)rs[j] * NTOT + nc + cp[j]];

        for (int kt0 = 0; kt0 < KIN; kt0 += KTE) {
            #pragma unroll
            for (int j = 0; j < 3; j++) {
                float4 d; d.x = pf[j].x; d.y = pf[j].x; d.z = pf[j].y; d.w = pf[j].y;
                *(float4*)&wt[rs[j] * 384 + cp[j] * 2] = d;
            }
            __syncthreads();
            if (kt0 + KTE < KIN) {
                #pragma unroll
                for (int j = 0; j < 3; j++)
                    pf[j] = *(const float2*)&Wg[(size_t)(kt0 + KTE + rs[j]) * NTOT + nc + cp[j]];
            }
            #pragma unroll
            for (int kk = 0; kk < KTE; kk++) {
                const float* srow = src + (kt0 + kk) * SROW + 8 * ty;
                ulonglong2 aA = *(const ulonglong2*)srow;
                ulonglong2 aB = *(const ulonglong2*)(srow + 4);
                u64 a0 = aA.x, a1 = aA.y, a2 = aB.x, a3 = aB.y;
                const float* wrow = wt + kk * 384 + tx * 8;
                ulonglong2 bp0 = *(const ulonglong2*)wrow;        // (w0,w0),(w1,w1)
                ulonglong2 bp1 = *(const ulonglong2*)(wrow + 4);  // (w2,w2),(w3,w3)
                u64 b0 = bp0.x, b1 = bp0.y, b2 = bp1.x, b3 = bp1.y;
                acc[0][0]=fma2(a0,b0,acc[0][0]); acc[0][1]=fma2(a0,b1,acc[0][1]); acc[0][2]=fma2(a0,b2,acc[0][2]); acc[0][3]=fma2(a0,b3,acc[0][3]);
                acc[1][0]=fma2(a1,b0,acc[1][0]); acc[1][1]=fma2(a1,b1,acc[1][1]); acc[1][2]=fma2(a1,b2,acc[1][2]); acc[1][3]=fma2(a1,b3,acc[1][3]);
                acc[2][0]=fma2(a2,b0,acc[2][0]); acc[2][1]=fma2(a2,b1,acc[2][1]); acc[2][2]=fma2(a2,b2,acc[2][2]); acc[2][3]=fma2(a2,b3,acc[2][3]);
                acc[3][0]=fma2(a3,b0,acc[3][0]); acc[3][1]=fma2(a3,b1,acc[3][1]); acc[3][2]=fma2(a3,b2,acc[3][2]); acc[3][3]=fma2(a3,b3,acc[3][3]);
            }
            __syncthreads();
        }
        #pragma unroll
        for (int ci = 0; ci < 4; ci++) {
            int col = nc + tx * 4 + ci;
            float bb = bg[col];
            u64 st[4];
            #pragma unroll
            for (int p = 0; p < 4; p++) {
                float lo, hi; upk2(acc[p][ci], lo, hi);
                lo += bb; hi += bb;
                if (DOGELU) { lo = gelu_f(lo); hi = gelu_f(hi); }
                st[p] = pk2(lo, hi);
            }
            ulonglong2* dp = (ulonglong2*)&dst[(size_t)col * SROW + 8 * ty];
            dp[0] = make_ulonglong2(st[0], st[1]);
            dp[1] = make_ulonglong2(st[2], st[3]);
        }
    }
}

// ---------- small kernels ----------
__global__ void k_detect(const int* __restrict__ E32) {
    if (threadIdx.x == 0) {
        int mode = 1;
        for (int i = 1; i < 128; i += 2) if (E32[i] != 0) { mode = 0; break; }
        g_edge64 = mode;
    }
}

__global__ void k_embed(const float* __restrict__ qp) {
    int q = blockIdx.x, t = threadIdx.x;
    int d = t >> 5, j = t & 31;
    float c = qp[q * 3 + d];
    float omega = exp2f(-(float)j * 0.41524101186092029f);
    float s, co; sincosf(c * omega, &s, &co);
    g_qe[(size_t)q * C + d * 64 + j]      = s;
    g_qe[(size_t)q * C + d * 64 + 32 + j] = co;
}

// Cw[i][n] = sum_j Pw[i][j] * W0[j][n] ; cb[n] = sum_j Pb[j] * W0[j][n]
__global__ void k_cw(const float* __restrict__ Pw, const float* __restrict__ Pb,
                     const float* __restrict__ W0) {
    __shared__ float row[C];
    int i = blockIdx.x, n = threadIdx.x;
    const float* src = (i < C) ? (Pw + (size_t)i * C) : Pb;
    for (int j = n; j < C; j += C2) row[j] = src[j];
    __syncthreads();
    float s = 0.0f;
    #pragma unroll 8
    for (int j = 0; j < C; j++) s += row[j] * W0[(size_t)j * C2 + n];
    if (i < C) g_cw[(size_t)i * C2 + n] = s;
    else       g_cb[n] = s;
}

__global__ void k_zero() {
    int idx = blockIdx.x * blockDim.x + threadIdx.x;
    int stride = gridDim.x * blockDim.x;
    for (int i = idx; i < NQ * C2; i += stride) g_seg[i] = 0.0f;
    for (int i = idx; i < NQ; i += stride) g_cnt[i] = 0;
}

// ---------- generic 192->384 tile GEMM body ----------
__device__ __forceinline__ void lin384_body(int r0, const float* __restrict__ src,
                                            const float* __restrict__ W,
                                            const float* __restrict__ bg,
                                            float* __restrict__ dst)
{
    extern __shared__ float sm[];
    float* bufA = sm;                    // [192][SROW]
    float* bufB = bufA + C * SROW;       // [384][SROW]
    float* wt   = bufB + C2 * SROW;      // KT*192
    int tid = threadIdx.x;
    int e = tid / 6, t2 = tid % 6;
    {
        const float* s = src + (size_t)(r0 + e) * C + t2 * 32;
        int cbase = t2 * 32;
        #pragma unroll
        for (int i = 0; i < 8; i++) {
            float4 v = *(const float4*)(s + i * 4);
            int c = cbase + i * 4;
            bufA[(c+0)*SROW+e]=v.x; bufA[(c+1)*SROW+e]=v.y; bufA[(c+2)*SROW+e]=v.z; bufA[(c+3)*SROW+e]=v.w;
        }
    }
    __syncthreads();
    layer_mlp<C, C2, false>(W, bg, bufA, bufB, wt, tid);
    __syncthreads();
    {
        int cb = t2 * 64;
        float* drow = dst + (size_t)(r0 + e) * C2 + cb;
        #pragma unroll
        for (int i = 0; i < 16; i++) {
            float4 v;
            v.x = bufB[(size_t)(cb + i*4 + 0) * SROW + e];
            v.y = bufB[(size_t)(cb + i*4 + 1) * SROW + e];
            v.z = bufB[(size_t)(cb + i*4 + 2) * SROW + e];
            v.w = bufB[(size_t)(cb + i*4 + 3) * SROW + e];
            *(float4*)(drow + i * 4) = v;
        }
    }
}

__global__ void __launch_bounds__(NTHR, 1) k_ux(const float* __restrict__ x) {
    lin384_body(blockIdx.x * TILE, x, g_cw, g_cb, g_u);
}
__global__ void __launch_bounds__(NTHR, 1) k_vx(const float* __restrict__ m0w,
                                                const float* __restrict__ m0b) {
    lin384_body(blockIdx.x * TILE, g_qe, m0w + (size_t)C * C2, m0b, g_v);
}

// ---------- fused edge kernel: gelu(U[g]+V[q]) -> L1 GEMM+gelu -> 384-wide segment sum ----------
__global__ void __launch_bounds__(NTHR, 1) k_edges2(const void* __restrict__ Eg,
    const float* __restrict__ W1, const float* __restrict__ b1)
{
    extern __shared__ float sm[];
    float* bufA = sm;                     // [384][SROW]
    float* bufB = bufA + C2 * SROW;       // [384][SROW]
    float* wt   = bufB + C2 * SROW;       // KTE*384 (dup)
    int* qs = (int*)(wt + KTE * 384);     // [64]
    int tid = threadIdx.x;
    int e0 = blockIdx.x * TILE;
    {
        int e = tid / 6, t2 = tid % 6;
        int q, g; load_edge(Eg, e0 + e, q, g);
        if (t2 == 0) qs[e] = q;
        const float4* up = (const float4*)(g_u + (size_t)g * C2 + t2 * 64);
        const float4* vp = (const float4*)(g_v + (size_t)q * C2 + t2 * 64);
        int kb = t2 * 64;
        #pragma unroll 4
        for (int i = 0; i < 16; i++) {
            float4 a = up[i], b = vp[i];
            int k = kb + i * 4;
            bufA[(k+0)*SROW+e] = gelu_f(a.x + b.x);
            bufA[(k+1)*SROW+e] = gelu_f(a.y + b.y);
            bufA[(k+2)*SROW+e] = gelu_f(a.z + b.z);
            bufA[(k+3)*SROW+e] = gelu_f(a.w + b.w);
        }
    }
    __syncthreads();
    layer_mlp_dup<C2, C2, true>(W1, b1, bufA, bufB, wt, tid);
    __syncthreads();
    // segment-sum (sorted qidx -> contiguous runs); 384 threads = 384 columns
    {
        int c = tid;
        int cur = qs[0];
        float s = bufB[(size_t)c * SROW + 0];
        for (int e = 1; e < TILE; e++) {
            int q = qs[e];
            float v = bufB[(size_t)c * SROW + e];
            if (q == cur) s += v;
            else { atomicAdd(&g_seg[(size_t)cur * C2 + c], s); cur = q; s = v; }
        }
        atomicAdd(&g_seg[(size_t)cur * C2 + c], s);
    }
    if (tid == 0) {
        int cur = qs[0], n = 1;
        for (int e = 1; e < TILE; e++) {
            int q = qs[e];
            if (q == cur) n++;
            else { atomicAdd(&g_cnt[cur], n); cur = q; n = 1; }
        }
        atomicAdd(&g_cnt[cur], n);
    }
}

// ---------- per-query tail: m = (S@W2)/cnt + b2 (cnt>0, else 0) ; out = gelu(m@p0+b)@p1+b ----------
__global__ void __launch_bounds__(NTHR, 1) k_pred2(
    const float* __restrict__ W2, const float* __restrict__ b2,
    const float* __restrict__ p0w, const float* __restrict__ p0b,
    const float* __restrict__ p1w, const float* __restrict__ p1b,
    float* __restrict__ out)
{
    extern __shared__ float sm[];
    float* bufA = sm;                    // [384][SROW]
    float* bufB = bufA + C2 * SROW;      // [192][SROW]
    float* wt   = bufB + C * SROW;       // KT*192
    int* czero  = (int*)(wt + KT * 192); // [64]
    int tid = threadIdx.x;
    int q0 = blockIdx.x * TILE;
    {
        int e = tid / 6, t2 = tid % 6;
        int q = q0 + e;
        int cnt = g_cnt[q];
        float inv = 1.0f / fmaxf((float)cnt, 1.0f);
        if (t2 == 0) czero[e] = (cnt == 0);
        const float4* sp = (const float4*)(g_seg + (size_t)q * C2 + t2 * 64);
        int kb = t2 * 64;
        #pragma unroll
        for (int i = 0; i < 16; i++) {
            float4 v = sp[i];
            int k = kb + i * 4;
            bufA[(k+0)*SROW+e]=v.x*inv; bufA[(k+1)*SROW+e]=v.y*inv;
            bufA[(k+2)*SROW+e]=v.z*inv; bufA[(k+3)*SROW+e]=v.w*inv;
        }
    }
    __syncthreads();
    layer_mlp<C2, C, false>(W2, b2, bufA, bufB, wt, tid);
    __syncthreads();
    {   // zero rows with cnt==0 (reference: m = 0 there)
        int e = tid & 63, ch = tid / 64;   // 6 chunks x 32 cols
        if (czero[e]) {
            #pragma unroll
            for (int j = 0; j < 32; j++) bufB[(size_t)(ch * 32 + j) * SROW + e] = 0.0f;
        }
    }
    __syncthreads();
    layer_mlp<C, C, true>(p0w, p0b, bufB, bufA, wt, tid);
    __syncthreads();
    if (tid < 256) {
        int q = tid >> 2, o = tid & 3;
        float s = p1b[o];
        #pragma unroll 8
        for (int k = 0; k < C; k++)
            s += bufA[(size_t)k * SROW + q] * p1w[k * 4 + o];
        out[(size_t)(q0 + q) * 4 + o] = s;
    }
}

extern "C" void kernel_launch(void* const* d_in, const int* in_sizes, int n_in,
                              void* d_out, int out_size)
{
    const float* x      = (const float*)d_in[0];
    const float* qp     = (const float*)d_in[1];
    const void*  E      = d_in[2];
    const float* proj_w = (const float*)d_in[3];
    const float* proj_b = (const float*)d_in[4];
    const float* m0w    = (const float*)d_in[5];
    const float* m0b    = (const float*)d_in[6];
    const float* m1w    = (const float*)d_in[7];
    const float* m1b    = (const float*)d_in[8];
    const float* m2w    = (const float*)d_in[9];
    const float* m2b    = (const float*)d_in[10];
    const float* p0w    = (const float*)d_in[11];
    const float* p0b    = (const float*)d_in[12];
    const float* p1w    = (const float*)d_in[13];
    const float* p1b    = (const float*)d_in[14];
    float* out = (float*)d_out;

    const int SM_LIN  = (C * SROW + C2 * SROW + KT * 192) * 4;            // 175,104
    const int SM_EDGE = (2 * C2 * SROW + KTE * 384) * 4 + TILE * 4;       // 227,584
    const int SM_PRED = (C2 * SROW + C * SROW + KT * 192) * 4 + TILE * 4; // 175,360

    cudaFuncSetAttribute(k_ux,     cudaFuncAttributeMaxDynamicSharedMemorySize, SM_LIN);
    cudaFuncSetAttribute(k_vx,     cudaFuncAttributeMaxDynamicSharedMemorySize, SM_LIN);
    cudaFuncSetAttribute(k_edges2, cudaFuncAttributeMaxDynamicSharedMemorySize, SM_EDGE);
    cudaFuncSetAttribute(k_pred2,  cudaFuncAttributeMaxDynamicSharedMemorySize, SM_PRED);

    k_detect<<<1, 32>>>((const int*)E);
    k_embed<<<NQ, 96>>>(qp);
    k_cw<<<C + 1, C2>>>(proj_w, proj_b, m0w);
    k_ux<<<SGRID / TILE, NTHR, SM_LIN>>>(x);
    k_vx<<<NQ / TILE, NTHR, SM_LIN>>>(m0w, m0b);
    k_zero<<<2048, 256>>>();
    k_edges2<<<NEDGE / TILE, NTHR, SM_EDGE>>>(E, m1w, m1b);
    k_pred2<<<NQ / TILE, NTHR, SM_PRED>>>(m2w, m2b, p0w, p0b, p1w, p1b, out);
}

// round 16
// speedup vs baseline: 1.7664x; 1.7664x over previous
#include <cuda_runtime.h>
#include <cstdint>

typedef unsigned long long u64;

#define NQ 32768
#define SGRID 32768
#define NEDGE 262144
#define C 192
#define C2 384
#define IDXMASK 32767
#define TILE 64
#define NTHR 384
#define KT 24     // k-block for 192-wide staging (k_uv / k_pred2)
#define KTE 12    // k-block for 384-wide staging (k_edges2 single-pass)
#define SROW 68   // floats; 272 B row stride (16B aligned for LDS.128)

// Scratch (device globals; no allocation allowed)
__device__ __align__(16) float g_u[(size_t)SGRID * C2];    // x @ Cw + cb
__device__ __align__(16) float g_v[(size_t)NQ * C2];       // qe @ W0_bot + b0 (qe inlined)
__device__ __align__(16) float g_seg[(size_t)NQ * C2];     // seg_sum of h1 (384-wide)
__device__ __align__(16) float g_cw[C * C2];               // proj_w @ W0_top
__device__ __align__(16) float g_cb[C2];                   // proj_b @ W0_top
__device__ int g_cnt[NQ];
__device__ int g_edge64;

// ---------- helpers ----------
__device__ __forceinline__ float gelu_f(float x) {
    return 0.5f * x * (1.0f + erff(x * 0.7071067811865476f));
}
__device__ __forceinline__ void load_edge(const void* Eg, int e, int& q, int& g) {
    if (g_edge64) {
        const long long* E = (const long long*)Eg;
        q = (int)E[2 * (size_t)e] & IDXMASK; g = (int)E[2 * (size_t)e + 1] & IDXMASK;
    } else {
        const int* E = (const int*)Eg;
        q = E[2 * (size_t)e] & IDXMASK; g = E[2 * (size_t)e + 1] & IDXMASK;
    }
}
__device__ __forceinline__ u64 pk2(float lo, float hi) { u64 r; asm("mov.b64 %0,{%1,%2};" : "=l"(r) : "f"(lo), "f"(hi)); return r; }
__device__ __forceinline__ void upk2(u64 v, float& lo, float& hi) { asm("mov.b64 {%0,%1},%2;" : "=f"(lo), "=f"(hi) : "l"(v)); }
__device__ __forceinline__ u64 fma2(u64 a, u64 b, u64 c) { u64 d; asm("fma.rn.f32x2 %0,%1,%2,%3;" : "=l"(d) : "l"(a), "l"(b), "l"(c)); return d; }

// ---------- R9 layer_mlp (unchanged — best known) ----------
template<int KIN, int NTOT, bool DOGELU>
__device__ __forceinline__ void layer_mlp(const float* __restrict__ Wg, const float* __restrict__ bg,
                                          const float* src, float* dst, float* wt, int tid)
{
    const int tx = tid % 48, ty = tid / 48;
    int rs[3], cs[3];
    #pragma unroll
    for (int j = 0; j < 3; j++) { int f = tid + j * NTHR; rs[j] = f / 48; cs[j] = (f % 48) * 4; }

    for (int nc = 0; nc < NTOT; nc += 192) {
        u64 acc[4][4];
        #pragma unroll
        for (int p = 0; p < 4; p++)
            #pragma unroll
            for (int ci = 0; ci < 4; ci++) acc[p][ci] = 0ull;

        float4 pf[3];
        #pragma unroll
        for (int j = 0; j < 3; j++)
            pf[j] = *(const float4*)&Wg[(size_t)rs[j] * NTOT + nc + cs[j]];

        for (int kt0 = 0; kt0 < KIN; kt0 += KT) {
            #pragma unroll
            for (int j = 0; j < 3; j++)
                *(float4*)&wt[rs[j] * 192 + cs[j]] = pf[j];
            __syncthreads();
            if (kt0 + KT < KIN) {
                #pragma unroll
                for (int j = 0; j < 3; j++)
                    pf[j] = *(const float4*)&Wg[(size_t)(kt0 + KT + rs[j]) * NTOT + nc + cs[j]];
            }
            #pragma unroll
            for (int kk = 0; kk < KT; kk++) {
                const float* srow = src + (kt0 + kk) * SROW + 8 * ty;
                ulonglong2 aA = *(const ulonglong2*)srow;
                ulonglong2 aB = *(const ulonglong2*)(srow + 4);
                u64 a0 = aA.x, a1 = aA.y, a2 = aB.x, a3 = aB.y;
                float4 bv = *(const float4*)&wt[kk * 192 + tx * 4];
                u64 b0 = pk2(bv.x, bv.x), b1 = pk2(bv.y, bv.y), b2 = pk2(bv.z, bv.z), b3 = pk2(bv.w, bv.w);
                acc[0][0]=fma2(a0,b0,acc[0][0]); acc[0][1]=fma2(a0,b1,acc[0][1]); acc[0][2]=fma2(a0,b2,acc[0][2]); acc[0][3]=fma2(a0,b3,acc[0][3]);
                acc[1][0]=fma2(a1,b0,acc[1][0]); acc[1][1]=fma2(a1,b1,acc[1][1]); acc[1][2]=fma2(a1,b2,acc[1][2]); acc[1][3]=fma2(a1,b3,acc[1][3]);
                acc[2][0]=fma2(a2,b0,acc[2][0]); acc[2][1]=fma2(a2,b1,acc[2][1]); acc[2][2]=fma2(a2,b2,acc[2][2]); acc[2][3]=fma2(a2,b3,acc[2][3]);
                acc[3][0]=fma2(a3,b0,acc[3][0]); acc[3][1]=fma2(a3,b1,acc[3][1]); acc[3][2]=fma2(a3,b2,acc[3][2]); acc[3][3]=fma2(a3,b3,acc[3][3]);
            }
            __syncthreads();
        }
        #pragma unroll
        for (int ci = 0; ci < 4; ci++) {
            int col = nc + tx * 4 + ci;
            float bb = bg[col];
            u64 st[4];
            #pragma unroll
            for (int p = 0; p < 4; p++) {
                float lo, hi; upk2(acc[p][ci], lo, hi);
                lo += bb; hi += bb;
                if (DOGELU) { lo = gelu_f(lo); hi = gelu_f(hi); }
                st[p] = pk2(lo, hi);
            }
            ulonglong2* dp = (ulonglong2*)&dst[(size_t)col * SROW + 8 * ty];
            dp[0] = make_ulonglong2(st[0], st[1]);
            dp[1] = make_ulonglong2(st[2], st[3]);
        }
    }
}

// ---------- single-pass full-width edge layer (KIN=384 -> NTOT=384) ----------
// acc covers cols {tx*4..+3} and {192+tx*4..+3}: each bufA k-row read ONCE.
// b-loads: two contiguous 16B-stride LDS.128 (4 phases each, conflict-free).
// wt: [KTE][384]; staging 3 float4/thread, register-prefetched.
__device__ __forceinline__ void layer_edge(const float* __restrict__ Wg, const float* __restrict__ bg,
                                           const float* src, float* dst, float* wt, int tid)
{
    const int tx = tid % 48, ty = tid / 48;
    int rs[3], cs[3];
    #pragma unroll
    for (int j = 0; j < 3; j++) { int f = tid + j * NTHR; rs[j] = f / 96; cs[j] = (f % 96) * 4; }

    u64 acc[4][8];
    #pragma unroll
    for (int p = 0; p < 4; p++)
        #pragma unroll
        for (int ci = 0; ci < 8; ci++) acc[p][ci] = 0ull;

    float4 pf[3];
    #pragma unroll
    for (int j = 0; j < 3; j++)
        pf[j] = *(const float4*)&Wg[(size_t)rs[j] * C2 + cs[j]];

    for (int kt0 = 0; kt0 < C2; kt0 += KTE) {
        #pragma unroll
        for (int j = 0; j < 3; j++)
            *(float4*)&wt[rs[j] * 384 + cs[j]] = pf[j];
        __syncthreads();
        if (kt0 + KTE < C2) {
            #pragma unroll
            for (int j = 0; j < 3; j++)
                pf[j] = *(const float4*)&Wg[(size_t)(kt0 + KTE + rs[j]) * C2 + cs[j]];
        }
        #pragma unroll
        for (int kk = 0; kk < KTE; kk++) {
            const float* srow = src + (kt0 + kk) * SROW + 8 * ty;
            ulonglong2 aA = *(const ulonglong2*)srow;
            ulonglong2 aB = *(const ulonglong2*)(srow + 4);
            u64 a0 = aA.x, a1 = aA.y, a2 = aB.x, a3 = aB.y;
            float4 bv0 = *(const float4*)&wt[kk * 384 + tx * 4];
            float4 bv1 = *(const float4*)&wt[kk * 384 + 192 + tx * 4];
            u64 b0 = pk2(bv0.x, bv0.x), b1 = pk2(bv0.y, bv0.y), b2 = pk2(bv0.z, bv0.z), b3 = pk2(bv0.w, bv0.w);
            u64 b4 = pk2(bv1.x, bv1.x), b5 = pk2(bv1.y, bv1.y), b6 = pk2(bv1.z, bv1.z), b7 = pk2(bv1.w, bv1.w);
            acc[0][0]=fma2(a0,b0,acc[0][0]); acc[0][1]=fma2(a0,b1,acc[0][1]); acc[0][2]=fma2(a0,b2,acc[0][2]); acc[0][3]=fma2(a0,b3,acc[0][3]);
            acc[1][0]=fma2(a1,b0,acc[1][0]); acc[1][1]=fma2(a1,b1,acc[1][1]); acc[1][2]=fma2(a1,b2,acc[1][2]); acc[1][3]=fma2(a1,b3,acc[1][3]);
            acc[2][0]=fma2(a2,b0,acc[2][0]); acc[2][1]=fma2(a2,b1,acc[2][1]); acc[2][2]=fma2(a2,b2,acc[2][2]); acc[2][3]=fma2(a2,b3,acc[2][3]);
            acc[3][0]=fma2(a3,b0,acc[3][0]); acc[3][1]=fma2(a3,b1,acc[3][1]); acc[3][2]=fma2(a3,b2,acc[3][2]); acc[3][3]=fma2(a3,b3,acc[3][3]);
            acc[0][4]=fma2(a0,b4,acc[0][4]); acc[0][5]=fma2(a0,b5,acc[0][5]); acc[0][6]=fma2(a0,b6,acc[0][6]); acc[0][7]=fma2(a0,b7,acc[0][7]);
            acc[1][4]=fma2(a1,b4,acc[1][4]); acc[1][5]=fma2(a1,b5,acc[1][5]); acc[1][6]=fma2(a1,b6,acc[1][6]); acc[1][7]=fma2(a1,b7,acc[1][7]);
            acc[2][4]=fma2(a2,b4,acc[2][4]); acc[2][5]=fma2(a2,b5,acc[2][5]); acc[2][6]=fma2(a2,b6,acc[2][6]); acc[2][7]=fma2(a2,b7,acc[2][7]);
            acc[3][4]=fma2(a3,b4,acc[3][4]); acc[3][5]=fma2(a3,b5,acc[3][5]); acc[3][6]=fma2(a3,b6,acc[3][6]); acc[3][7]=fma2(a3,b7,acc[3][7]);
        }
        __syncthreads();
    }
    #pragma unroll
    for (int half = 0; half < 2; half++) {
        #pragma unroll
        for (int ci = 0; ci < 4; ci++) {
            int col = half * 192 + tx * 4 + ci;
            float bb = bg[col];
            u64 st[4];
            #pragma unroll
            for (int p = 0; p < 4; p++) {
                float lo, hi; upk2(acc[p][half * 4 + ci], lo, hi);
                lo = gelu_f(lo + bb); hi = gelu_f(hi + bb);
                st[p] = pk2(lo, hi);
            }
            ulonglong2* dp = (ulonglong2*)&dst[(size_t)col * SROW + 8 * ty];
            dp[0] = make_ulonglong2(st[0], st[1]);
            dp[1] = make_ulonglong2(st[2], st[3]);
        }
    }
}

// ---------- init: edge-dtype detect + zero accumulators ----------
__global__ void k_init(const int* __restrict__ E32) {
    int idx = blockIdx.x * blockDim.x + threadIdx.x;
    if (idx == 0) {
        int mode = 1;
        for (int i = 1; i < 128; i += 2) if (E32[i] != 0) { mode = 0; break; }
        g_edge64 = mode;
    }
    int stride = gridDim.x * blockDim.x;
    for (int i = idx; i < NQ * C2; i += stride) g_seg[i] = 0.0f;
    for (int i = idx; i < NQ; i += stride) g_cnt[i] = 0;
}

// Cw[i][n] = sum_j Pw[i][j] * W0[j][n] ; cb[n] = sum_j Pb[j] * W0[j][n]
__global__ void k_cw(const float* __restrict__ Pw, const float* __restrict__ Pb,
                     const float* __restrict__ W0) {
    __shared__ float row[C];
    int i = blockIdx.x, n = threadIdx.x;
    const float* src = (i < C) ? (Pw + (size_t)i * C) : Pb;
    for (int j = n; j < C; j += C2) row[j] = src[j];
    __syncthreads();
    float s = 0.0f;
    #pragma unroll 8
    for (int j = 0; j < C; j++) s += row[j] * W0[(size_t)j * C2 + n];
    if (i < C) g_cw[(size_t)i * C2 + n] = s;
    else       g_cb[n] = s;
}

// ---------- fused U/V production (R9 GEMM core, embed inlined in V branch) ----------
__global__ void __launch_bounds__(NTHR, 1) k_uv(const float* __restrict__ x,
                                                const float* __restrict__ qp,
                                                const float* __restrict__ m0w,
                                                const float* __restrict__ m0b)
{
    extern __shared__ float sm[];
    float* bufA = sm;                    // [192][SROW]
    float* bufB = bufA + C * SROW;       // [384][SROW]
    float* wt   = bufB + C2 * SROW;      // KT*192
    int tid = threadIdx.x;
    int b = blockIdx.x;
    int isV = (b >= SGRID / TILE);
    int r0 = (isV ? b - SGRID / TILE : b) * TILE;
    int e = tid / 6, t2 = tid % 6;
    if (!isV) {
        const float* s = x + (size_t)(r0 + e) * C + t2 * 32;
        int cbase = t2 * 32;
        #pragma unroll
        for (int i = 0; i < 8; i++) {
            float4 v = *(const float4*)(s + i * 4);
            int c = cbase + i * 4;
            bufA[(c+0)*SROW+e]=v.x; bufA[(c+1)*SROW+e]=v.y; bufA[(c+2)*SROW+e]=v.z; bufA[(c+3)*SROW+e]=v.w;
        }
    } else {
        // inline sincos embedding: cols t2*32..+31, d = t2/2, sin if t2 even else cos
        float coord = qp[(size_t)(r0 + e) * 3 + (t2 >> 1)];
        int odd = t2 & 1;
        int cbase = t2 * 32;
        #pragma unroll 8
        for (int i = 0; i < 32; i++) {
            float arg = coord * exp2f(-(float)i * 0.41524101186092029f);
            float val = odd ? cosf(arg) : sinf(arg);
            bufA[(cbase + i) * SROW + e] = val;
        }
    }
    __syncthreads();
    if (!isV) layer_mlp<C, C2, false>(g_cw, g_cb, bufA, bufB, wt, tid);
    else      layer_mlp<C, C2, false>(m0w + (size_t)C * C2, m0b, bufA, bufB, wt, tid);
    __syncthreads();
    {
        float* dst = isV ? g_v : g_u;
        int cb = t2 * 64;
        float* drow = dst + (size_t)(r0 + e) * C2 + cb;
        #pragma unroll
        for (int i = 0; i < 16; i++) {
            float4 v;
            v.x = bufB[(size_t)(cb + i*4 + 0) * SROW + e];
            v.y = bufB[(size_t)(cb + i*4 + 1) * SROW + e];
            v.z = bufB[(size_t)(cb + i*4 + 2) * SROW + e];
            v.w = bufB[(size_t)(cb + i*4 + 3) * SROW + e];
            *(float4*)(drow + i * 4) = v;
        }
    }
}

// ---------- fused edge kernel: gelu(U[g]+V[q]) -> L1 (single-pass) -> segment sum ----------
__global__ void __launch_bounds__(NTHR, 1) k_edges2(const void* __restrict__ Eg,
    const float* __restrict__ W1, const float* __restrict__ b1)
{
    extern __shared__ float sm[];
    float* bufA = sm;                     // [384][SROW]
    float* bufB = bufA + C2 * SROW;       // [384][SROW]
    float* wt   = bufB + C2 * SROW;       // KTE*384
    int* qs = (int*)(wt + KTE * 384);     // [64]
    int tid = threadIdx.x;
    int e0 = blockIdx.x * TILE;
    {
        int e = tid / 6, t2 = tid % 6;
        int q, g; load_edge(Eg, e0 + e, q, g);
        if (t2 == 0) qs[e] = q;
        const float4* up = (const float4*)(g_u + (size_t)g * C2 + t2 * 64);
        const float4* vp = (const float4*)(g_v + (size_t)q * C2 + t2 * 64);
        int kb = t2 * 64;
        #pragma unroll 4
        for (int i = 0; i < 16; i++) {
            float4 a = up[i], b = vp[i];
            int k = kb + i * 4;
            bufA[(k+0)*SROW+e] = gelu_f(a.x + b.x);
            bufA[(k+1)*SROW+e] = gelu_f(a.y + b.y);
            bufA[(k+2)*SROW+e] = gelu_f(a.z + b.z);
            bufA[(k+3)*SROW+e] = gelu_f(a.w + b.w);
        }
    }
    __syncthreads();
    layer_edge(W1, b1, bufA, bufB, wt, tid);
    __syncthreads();
    // segment-sum (sorted qidx -> contiguous runs); 384 threads = 384 columns
    {
        int c = tid;
        int cur = qs[0];
        float s = bufB[(size_t)c * SROW + 0];
        for (int e = 1; e < TILE; e++) {
            int q = qs[e];
            float v = bufB[(size_t)c * SROW + e];
            if (q == cur) s += v;
            else { atomicAdd(&g_seg[(size_t)cur * C2 + c], s); cur = q; s = v; }
        }
        atomicAdd(&g_seg[(size_t)cur * C2 + c], s);
    }
    if (tid == 0) {
        int cur = qs[0], n = 1;
        for (int e = 1; e < TILE; e++) {
            int q = qs[e];
            if (q == cur) n++;
            else { atomicAdd(&g_cnt[cur], n); cur = q; n = 1; }
        }
        atomicAdd(&g_cnt[cur], n);
    }
}

// ---------- per-query tail ----------
__global__ void __launch_bounds__(NTHR, 1) k_pred2(
    const float* __restrict__ W2, const float* __restrict__ b2,
    const float* __restrict__ p0w, const float* __restrict__ p0b,
    const float* __restrict__ p1w, const float* __restrict__ p1b,
    float* __restrict__ out)
{
    extern __shared__ float sm[];
    float* bufA = sm;                    // [384][SROW]
    float* bufB = bufA + C2 * SROW;      // [192][SROW]
    float* wt   = bufB + C * SROW;       // KT*192
    int* czero  = (int*)(wt + KT * 192); // [64]
    int tid = threadIdx.x;
    int q0 = blockIdx.x * TILE;
    {
        int e = tid / 6, t2 = tid % 6;
        int q = q0 + e;
        int cnt = g_cnt[q];
        float inv = 1.0f / fmaxf((float)cnt, 1.0f);
        if (t2 == 0) czero[e] = (cnt == 0);
        const float4* sp = (const float4*)(g_seg + (size_t)q * C2 + t2 * 64);
        int kb = t2 * 64;
        #pragma unroll
        for (int i = 0; i < 16; i++) {
            float4 v = sp[i];
            int k = kb + i * 4;
            bufA[(k+0)*SROW+e]=v.x*inv; bufA[(k+1)*SROW+e]=v.y*inv;
            bufA[(k+2)*SROW+e]=v.z*inv; bufA[(k+3)*SROW+e]=v.w*inv;
        }
    }
    __syncthreads();
    layer_mlp<C2, C, false>(W2, b2, bufA, bufB, wt, tid);
    __syncthreads();
    {   // zero rows with cnt==0 (reference: m = 0 there)
        int e = tid & 63, ch = tid / 64;   // 6 chunks x 32 cols
        if (czero[e]) {
            #pragma unroll
            for (int j = 0; j < 32; j++) bufB[(size_t)(ch * 32 + j) * SROW + e] = 0.0f;
        }
    }
    __syncthreads();
    layer_mlp<C, C, true>(p0w, p0b, bufB, bufA, wt, tid);
    __syncthreads();
    if (tid < 256) {
        int q = tid >> 2, o = tid & 3;
        float s = p1b[o];
        #pragma unroll 8
        for (int k = 0; k < C; k++)
            s += bufA[(size_t)k * SROW + q] * p1w[k * 4 + o];
        out[(size_t)(q0 + q) * 4 + o] = s;
    }
}

extern "C" void kernel_launch(void* const* d_in, const int* in_sizes, int n_in,
                              void* d_out, int out_size)
{
    const float* x      = (const float*)d_in[0];
    const float* qp     = (const float*)d_in[1];
    const void*  E      = d_in[2];
    const float* proj_w = (const float*)d_in[3];
    const float* proj_b = (const float*)d_in[4];
    const float* m0w    = (const float*)d_in[5];
    const float* m0b    = (const float*)d_in[6];
    const float* m1w    = (const float*)d_in[7];
    const float* m1b    = (const float*)d_in[8];
    const float* m2w    = (const float*)d_in[9];
    const float* m2b    = (const float*)d_in[10];
    const float* p0w    = (const float*)d_in[11];
    const float* p0b    = (const float*)d_in[12];
    const float* p1w    = (const float*)d_in[13];
    const float* p1b    = (const float*)d_in[14];
    float* out = (float*)d_out;

    const int SM_LIN  = (C * SROW + C2 * SROW + KT * 192) * 4;            // 175,104
    const int SM_EDGE = (2 * C2 * SROW + KTE * 384) * 4 + TILE * 4;       // 227,584
    const int SM_PRED = (C2 * SROW + C * SROW + KT * 192) * 4 + TILE * 4; // 175,360

    cudaFuncSetAttribute(k_uv,     cudaFuncAttributeMaxDynamicSharedMemorySize, SM_LIN);
    cudaFuncSetAttribute(k_edges2, cudaFuncAttributeMaxDynamicSharedMemorySize, SM_EDGE);
    cudaFuncSetAttribute(k_pred2,  cudaFuncAttributeMaxDynamicSharedMemorySize, SM_PRED);

    k_init<<<2048, 256>>>((const int*)E);
    k_cw<<<C + 1, C2>>>(proj_w, proj_b, m0w);
    k_uv<<<(SGRID + NQ) / TILE, NTHR, SM_LIN>>>(x, qp, m0w, m0b);
    k_edges2<<<NEDGE / TILE, NTHR, SM_EDGE>>>(E, m1w, m1b);
    k_pred2<<<NQ / TILE, NTHR, SM_PRED>>>(m2w, m2b, p0w, p0b, p1w, p1b, out);
}